// round 13
// baseline (speedup 1.0000x reference)
#include <cuda_runtime.h>
#include <math.h>

#define BB   8
#define NN   4096
#define KK   20
#define HH   64
#define DOUT 64

#define QPB   128                // queries per block
#define SPLIT 2                  // lanes per query (candidate-range split)
#define TPB   (QPB * SPLIT)      // 256
#define SUBR  1024               // sub-range length (pad segment size)

#define BUFSLOTS 16
#define CLOUD_BYTES ((NN + 4) * 16)                 // float4[4100] = 65600
#define KNN_SMEM (CLOUD_BYTES + BUFSLOTS * TPB * 8) // + 32768 = 98368 B

// scratch for KNN indices (allocation-free rule: __device__ global)
__device__ int g_idx[BB * NN * KK];

__device__ __forceinline__ void topk_insert(float d, int m,
                                            float (&vals)[KK], int (&idxs)[KK],
                                            float& vmin, int& mslot) {
#pragma unroll
    for (int i = 0; i < KK; i++)
        if (i == mslot) { vals[i] = d; idxs[i] = m; }
    vmin = vals[0]; mslot = 0;
#pragma unroll
    for (int i = 1; i < KK; i++)
        if (vals[i] < vmin) { vmin = vals[i]; mslot = i; }
}

// branchless next-float-toward -inf; -inf maps to NaN which fmaxf suppresses
__device__ __forceinline__ float pred_f(float x) {
    const unsigned u = __float_as_uint(x);
    const unsigned up = (x > 0.0f) ? (u - 1u) : (u + 1u);
    return (x == 0.0f) ? -1.401298464e-45f : __uint_as_float(up);
}

// ---------------------------------------------------------------------------
// Kernel 1: brute-force KNN. 2 lanes split the candidate range per query.
// First 20 candidates seed the list via straight-line constant-index writes
// (no fill storm). Scan pushes gated by thr = max(vmin_own, pred(vmin_partner))
// -> d > thr === (d > vmin_own) && (d >= vmin_partner): prunes candidates that
// cannot survive the 2-list merge; pred keeps exact-tie semantics. SMEM
// candidate buffer [slot][tid]; lists merged with one shfl_down step.
// Ranking key: d' = 2*inner(n,m) - xx[m]  (== dist + xx[n], order-equivalent)
// ---------------------------------------------------------------------------
__global__ void __launch_bounds__(TPB) knn_kernel(const float* __restrict__ x) {
    extern __shared__ char smem[];
    float4* sx4  = reinterpret_cast<float4*>(smem);        // (x,y,z,-xx), pad/1024
    float2* sbuf = reinterpret_cast<float2*>(smem + CLOUD_BYTES);

    const int tid = threadIdx.x;
    const int b   = blockIdx.y;
    const int n0  = blockIdx.x * QPB;
    const float* xb = x + (size_t)b * 3 * NN;

    for (int i = tid; i < NN; i += TPB) {
        const float x0 = xb[i], x1 = xb[NN + i], x2 = xb[2 * NN + i];
        float w = -x0 * x0;
        w = fmaf(-x1, x1, w);
        w = fmaf(-x2, x2, w);
        sx4[i + (i >> 10)] = make_float4(x0, x1, x2, w);
    }
    __syncthreads();

    const int q = tid >> 1, s = tid & 1;
    const int n = n0 + q;
    const float4 ctr = sx4[n + (n >> 10)];
    const float a0 = 2.0f * ctr.x, a1 = 2.0f * ctr.y, a2 = 2.0f * ctr.z;

    float vals[KK];
    int   idxs[KK];
    float vmin;
    int   mslot = 0;
    int   cnt = 0;

    // ---- seed: first 24 candidates of segment 2s (direct constant-index
    //      writes for slots 0..19, normal insert for 20..23) ----
    {
        const float4* base0 = sx4 + (s * 2) * (SUBR + 1);
        const int mb0 = (s * 2) * SUBR;
#pragma unroll
        for (int i = 0; i < KK; i++) {
            const float4 p = base0[i];
            float dd = fmaf(a2, p.z, p.w);
            dd = fmaf(a1, p.y, dd);
            dd = fmaf(a0, p.x, dd);
            vals[i] = dd;
            idxs[i] = mb0 + i;
        }
        vmin = vals[0];
#pragma unroll
        for (int i = 1; i < KK; i++)
            if (vals[i] < vmin) { vmin = vals[i]; mslot = i; }
#pragma unroll
        for (int i = KK; i < 24; i++) {
            const float4 p = base0[i];
            float dd = fmaf(a2, p.z, p.w);
            dd = fmaf(a1, p.y, dd);
            dd = fmaf(a0, p.x, dd);
            if (dd > vmin)
                topk_insert(dd, mb0 + i, vals, idxs, vmin, mslot);
        }
    }
    const float pmin0 = __shfl_xor_sync(0xffffffffu, vmin, 1);
    float thr = fmaxf(vmin, pred_f(pmin0));

    // lane s covers sub-ranges 2s and 2s+1 (each 1024, pad-rebased pointers)
#pragma unroll 1
    for (int h = 0; h < 2; h++) {
        const int seg = s * 2 + h;
        const float4* base = sx4 + seg * (SUBR + 1);
        const int mbase = seg * SUBR;
        const int start = (h == 0) ? 24 : 0;

        for (int j0 = start; j0 < SUBR; j0 += 8) {
            float d[8];
#pragma unroll
            for (int u = 0; u < 8; u++) {
                const float4 p = base[j0 + u];
                float dd = fmaf(a2, p.z, p.w);
                dd = fmaf(a1, p.y, dd);
                dd = fmaf(a0, p.x, dd);
                d[u] = dd;
            }
#pragma unroll
            for (int u = 0; u < 8; u++) {
                if (d[u] > thr) {
                    sbuf[cnt * TPB + tid] =
                        make_float2(d[u], __int_as_float(mbase + j0 + u));
                    cnt++;
                }
            }
            if (__any_sync(0xffffffffu, cnt >= 8)) {
                for (int j = 0; j < cnt; j++) {
                    const float2 t = sbuf[j * TPB + tid];
                    if (t.x > vmin)
                        topk_insert(t.x, __float_as_int(t.y),
                                    vals, idxs, vmin, mslot);
                }
                cnt = 0;
                const float pmin = __shfl_xor_sync(0xffffffffu, vmin, 1);
                thr = fmaxf(vmin, pred_f(pmin));
            }
        }
    }
    for (int j = 0; j < cnt; j++) {
        const float2 t = sbuf[j * TPB + tid];
        if (t.x > vmin)
            topk_insert(t.x, __float_as_int(t.y), vals, idxs, vmin, mslot);
    }

    // ---- merge: lane s=0 (lower range) receives s=1's list; strict '>'
    // keeps the lowest index on exact ties (matches jax.lax.top_k).
#pragma unroll
    for (int i = 0; i < KK; i++) {
        const float rv = __shfl_down_sync(0xffffffffu, vals[i], 1);
        const int   ri = __shfl_down_sync(0xffffffffu, idxs[i], 1);
        if (s == 0 && rv > vmin)
            topk_insert(rv, ri, vals, idxs, vmin, mslot);
    }

    if (s == 0) {
        int* op = g_idx + ((size_t)b * NN + n) * KK;
#pragma unroll
        for (int i = 0; i < KK; i++) op[i] = idxs[i];
    }
}

// ---------------------------------------------------------------------------
// Kernel 2a: layer-1 (edge conv + BN + ReLU) + dual pooling.
// Thread = point, channel = loop -> coalesced m1/m2 stores, edge diffs in regs.
// ---------------------------------------------------------------------------
__global__ void __launch_bounds__(128) edgeA_kernel(
    const float* __restrict__ x,
    const float* __restrict__ w1,  const float* __restrict__ b1,
    const float* __restrict__ g1,  const float* __restrict__ beta1,
    const float* __restrict__ rm1, const float* __restrict__ rv1,
    float* __restrict__ m1o, float* __restrict__ m2o)
{
    __shared__ float sp[HH][8];   // W'*6, bias', pad

    const int tid = threadIdx.x;
    const int b = blockIdx.y;
    const int n = blockIdx.x * 128 + tid;

    if (tid < HH) {
        const float sc = __ldg(g1 + tid) * rsqrtf(__ldg(rv1 + tid) + 1e-5f);
#pragma unroll
        for (int c = 0; c < 6; c++) sp[tid][c] = __ldg(w1 + tid * 6 + c) * sc;
        sp[tid][6] = (__ldg(b1 + tid) - __ldg(rm1 + tid)) * sc + __ldg(beta1 + tid);
    }
    __syncthreads();

    const float* xb = x + (size_t)b * 3 * NN;
    const float c0 = xb[n];
    const float c1 = xb[NN + n];
    const float c2 = xb[2 * NN + n];

    const int* ip = g_idx + ((size_t)b * NN + n) * KK;
    float e0[KK], e1[KK], e2[KK];
#pragma unroll
    for (int k = 0; k < KK; k++) {
        const int m = __ldg(ip + k);
        e0[k] = __ldg(xb + m) - c0;
        e1[k] = __ldg(xb + NN + m) - c1;
        e2[k] = __ldg(xb + 2 * NN + m) - c2;
    }

    const size_t ob = (size_t)b * HH * NN + n;
#pragma unroll 2
    for (int h = 0; h < HH; h++) {
        const float W0 = sp[h][0], W1 = sp[h][1], W2 = sp[h][2];
        const float W3 = sp[h][3], W4 = sp[h][4], W5 = sp[h][5];
        float cd = sp[h][6];
        cd = fmaf(c0, W3, cd);
        cd = fmaf(c1, W4, cd);
        cd = fmaf(c2, W5, cd);

        float mx = -INFINITY, sm = 0.0f;
#pragma unroll
        for (int k = 0; k < KK; k++) {
            float dt = cd;
            dt = fmaf(e0[k], W0, dt);
            dt = fmaf(e1[k], W1, dt);
            dt = fmaf(e2[k], W2, dt);
            dt = fmaxf(dt, 0.0f);
            mx = fmaxf(mx, dt);
            sm += dt;
        }
        m1o[ob + (size_t)h * NN] = mx;
        m2o[ob + (size_t)h * NN] = sm * (1.0f / KK);
    }
}

// ---------------------------------------------------------------------------
// Kernel 2b: layer-2 GEMM: out[b,o,n] = ReLU(BN(sum_c w2[o,c]*cat[b,c,n]))
// 512 threads: 16 float4 n-groups x 32 o-bases, 2 outputs/thread.
// ---------------------------------------------------------------------------
__global__ void __launch_bounds__(512) edgeB_kernel(
    const float* __restrict__ m1o, const float* __restrict__ m2o,
    const float* __restrict__ w2,  const float* __restrict__ b2,
    const float* __restrict__ g2,  const float* __restrict__ beta2,
    const float* __restrict__ rm2, const float* __restrict__ rv2,
    float* __restrict__ out)
{
    __shared__ float sw[DOUT * 129];   // [o][c] padded rows
    __shared__ float ssc[DOUT], sbi[DOUT];

    const int tid = threadIdx.x;
    for (int i = tid; i < DOUT * 2 * HH; i += 512) {
        const int o = i >> 7, c = i & 127;
        sw[o * 129 + c] = __ldg(w2 + i);
    }
    if (tid < DOUT) {
        const float sc = __ldg(g2 + tid) * rsqrtf(__ldg(rv2 + tid) + 1e-5f);
        ssc[tid] = sc;
        sbi[tid] = (__ldg(b2 + tid) - __ldg(rm2 + tid)) * sc + __ldg(beta2 + tid);
    }
    __syncthreads();

    const int n4    = tid & 15;        // 16 float4 groups -> 64 n per block
    const int obase = tid >> 4;        // 0..31, thread covers o = obase+32j
    const int b  = blockIdx.y;
    const int n0 = blockIdx.x * 64 + n4 * 4;

    float4 acc[2];
#pragma unroll
    for (int j = 0; j < 2; j++) acc[j] = make_float4(0.f, 0.f, 0.f, 0.f);

    const float* cat0 = m1o + (size_t)b * HH * NN + n0;
    const float* cat1 = m2o + (size_t)b * HH * NN + n0;

#pragma unroll 4
    for (int c = 0; c < HH; c++) {
        const float4 v = __ldg(reinterpret_cast<const float4*>(cat0 + (size_t)c * NN));
#pragma unroll
        for (int j = 0; j < 2; j++) {
            const float w = sw[(obase + 32 * j) * 129 + c];
            acc[j].x = fmaf(w, v.x, acc[j].x);
            acc[j].y = fmaf(w, v.y, acc[j].y);
            acc[j].z = fmaf(w, v.z, acc[j].z);
            acc[j].w = fmaf(w, v.w, acc[j].w);
        }
    }
#pragma unroll 4
    for (int c = 0; c < HH; c++) {
        const float4 v = __ldg(reinterpret_cast<const float4*>(cat1 + (size_t)c * NN));
#pragma unroll
        for (int j = 0; j < 2; j++) {
            const float w = sw[(obase + 32 * j) * 129 + HH + c];
            acc[j].x = fmaf(w, v.x, acc[j].x);
            acc[j].y = fmaf(w, v.y, acc[j].y);
            acc[j].z = fmaf(w, v.z, acc[j].z);
            acc[j].w = fmaf(w, v.w, acc[j].w);
        }
    }

#pragma unroll
    for (int j = 0; j < 2; j++) {
        const int o = obase + 32 * j;
        const float sc = ssc[o], bi = sbi[o];
        float4 r;
        r.x = fmaxf(fmaf(acc[j].x, sc, bi), 0.0f);
        r.y = fmaxf(fmaf(acc[j].y, sc, bi), 0.0f);
        r.z = fmaxf(fmaf(acc[j].z, sc, bi), 0.0f);
        r.w = fmaxf(fmaf(acc[j].w, sc, bi), 0.0f);
        *reinterpret_cast<float4*>(out + ((size_t)b * DOUT + o) * NN + n0) = r;
    }
}

// ---------------------------------------------------------------------------
extern "C" void kernel_launch(void* const* d_in, const int* in_sizes, int n_in,
                              void* d_out, int out_size) {
    const float* x     = (const float*)d_in[0];
    const float* w1    = (const float*)d_in[1];
    const float* b1    = (const float*)d_in[2];
    const float* g1    = (const float*)d_in[3];
    const float* beta1 = (const float*)d_in[4];
    const float* rm1   = (const float*)d_in[5];
    const float* rv1   = (const float*)d_in[6];
    const float* w2    = (const float*)d_in[7];
    const float* b2    = (const float*)d_in[8];
    const float* g2    = (const float*)d_in[9];
    const float* beta2 = (const float*)d_in[10];
    const float* rm2   = (const float*)d_in[11];
    const float* rv2   = (const float*)d_in[12];

    float* out = (float*)d_out;
    float* m1o = out + (size_t)BB * HH * NN;
    float* m2o = m1o + (size_t)BB * HH * NN;

    cudaFuncSetAttribute(knn_kernel,
                         cudaFuncAttributeMaxDynamicSharedMemorySize, KNN_SMEM);

    knn_kernel<<<dim3(NN / QPB, BB), TPB, KNN_SMEM>>>(x);
    edgeA_kernel<<<dim3(NN / 128, BB), 128>>>(x, w1, b1, g1, beta1, rm1, rv1,
                                              m1o, m2o);
    edgeB_kernel<<<dim3(NN / 64, BB), 512>>>(m1o, m2o, w2, b2, g2, beta2,
                                             rm2, rv2, out);
}

// round 15
// speedup vs baseline: 1.8375x; 1.8375x over previous
#include <cuda_runtime.h>
#include <math.h>

#define BB   8
#define NN   4096
#define KK   20
#define HH   64
#define DOUT 64

#define QPB   64                 // queries per block
#define SPLIT 4                  // lanes per query (candidate-range split)
#define TPB   (QPB * SPLIT)      // 256
#define SUBR  1024               // sub-range length (pad segment size)

#define BUFSLOTS 16
#define CLOUD_BYTES ((NN + 4) * 16)                 // float4[4100] = 65600
#define KNN_SMEM (CLOUD_BYTES + BUFSLOTS * TPB * 8) // + 32768 = 98368 B

// scratch for KNN indices (allocation-free rule: __device__ global)
__device__ int g_idx[BB * NN * KK];

__device__ __forceinline__ void topk_insert(float d, int m,
                                            float (&vals)[KK], int (&idxs)[KK],
                                            float& vmin, int& mslot) {
#pragma unroll
    for (int i = 0; i < KK; i++)
        if (i == mslot) { vals[i] = d; idxs[i] = m; }
    vmin = vals[0]; mslot = 0;
#pragma unroll
    for (int i = 1; i < KK; i++)
        if (vals[i] < vmin) { vmin = vals[i]; mslot = i; }
}

// branchless next-float-toward -inf; -inf maps to NaN which fmaxf suppresses
__device__ __forceinline__ float pred_f(float x) {
    const unsigned u = __float_as_uint(x);
    const unsigned up = (x > 0.0f) ? (u - 1u) : (u + 1u);
    return (x == 0.0f) ? -1.401298464e-45f : __uint_as_float(up);
}

// ---------------------------------------------------------------------------
// Kernel 1: brute-force KNN. 4 lanes split the candidate range per query
// (lane s scans segment s of 1024). SMEM candidate buffer [slot][tid].
// Scan pushes gated by thr = max(vmin_own, pred(max over 4 lanes of vmin)):
// a candidate with d < vmin_j for any list j cannot be in the merged top-20
// (list j holds 20 values > d); pred keeps exact-tie (>=) semantics.
// Partial lists merged with two shfl_down rounds (lower range receives,
// strict '>' keeps lowest index on exact ties, matching jax.lax.top_k).
// Ranking key: d' = 2*inner(n,m) - xx[m]  (== dist + xx[n], order-equivalent)
// ---------------------------------------------------------------------------
__global__ void __launch_bounds__(TPB) knn_kernel(const float* __restrict__ x) {
    extern __shared__ char smem[];
    float4* sx4  = reinterpret_cast<float4*>(smem);        // (x,y,z,-xx), pad/1024
    float2* sbuf = reinterpret_cast<float2*>(smem + CLOUD_BYTES);

    const int tid = threadIdx.x;
    const int b   = blockIdx.y;
    const int n0  = blockIdx.x * QPB;
    const float* xb = x + (size_t)b * 3 * NN;

    for (int i = tid; i < NN; i += TPB) {
        const float x0 = xb[i], x1 = xb[NN + i], x2 = xb[2 * NN + i];
        float w = -x0 * x0;
        w = fmaf(-x1, x1, w);
        w = fmaf(-x2, x2, w);
        sx4[i + (i >> 10)] = make_float4(x0, x1, x2, w);
    }
    __syncthreads();

    const int q = tid >> 2, s = tid & 3;
    const int n = n0 + q;
    const float4 ctr = sx4[n + (n >> 10)];
    const float a0 = 2.0f * ctr.x, a1 = 2.0f * ctr.y, a2 = 2.0f * ctr.z;

    float vals[KK];
    int   idxs[KK];
#pragma unroll
    for (int i = 0; i < KK; i++) { vals[i] = -INFINITY; idxs[i] = 0; }
    float vmin = -INFINITY;
    float thr  = -INFINITY;
    int   mslot = 0;
    int   cnt = 0;

    const float4* base = sx4 + s * (SUBR + 1);
    const int mbase = s * SUBR;

    for (int j0 = 0; j0 < SUBR; j0 += 8) {
        float d[8];
#pragma unroll
        for (int u = 0; u < 8; u++) {
            const float4 p = base[j0 + u];
            float dd = fmaf(a2, p.z, p.w);
            dd = fmaf(a1, p.y, dd);
            dd = fmaf(a0, p.x, dd);
            d[u] = dd;
        }
#pragma unroll
        for (int u = 0; u < 8; u++) {
            if (d[u] > thr) {
                sbuf[cnt * TPB + tid] =
                    make_float2(d[u], __int_as_float(mbase + j0 + u));
                cnt++;
            }
        }
        if (__any_sync(0xffffffffu, cnt >= 8)) {
            for (int j = 0; j < cnt; j++) {
                const float2 t = sbuf[j * TPB + tid];
                if (t.x > vmin)
                    topk_insert(t.x, __float_as_int(t.y),
                                vals, idxs, vmin, mslot);
            }
            cnt = 0;
            float vmax = fmaxf(vmin, __shfl_xor_sync(0xffffffffu, vmin, 1));
            vmax = fmaxf(vmax, __shfl_xor_sync(0xffffffffu, vmax, 2));
            thr = fmaxf(vmin, pred_f(vmax));
        }
    }
    for (int j = 0; j < cnt; j++) {
        const float2 t = sbuf[j * TPB + tid];
        if (t.x > vmin)
            topk_insert(t.x, __float_as_int(t.y), vals, idxs, vmin, mslot);
    }

    // ---- shuffle-tree merge: s0<-s1, s2<-s3, then s0<-s2 ----
#pragma unroll
    for (int i = 0; i < KK; i++) {
        const float rv = __shfl_down_sync(0xffffffffu, vals[i], 1);
        const int   ri = __shfl_down_sync(0xffffffffu, idxs[i], 1);
        if ((s & 1) == 0 && rv > vmin)
            topk_insert(rv, ri, vals, idxs, vmin, mslot);
    }
#pragma unroll
    for (int i = 0; i < KK; i++) {
        const float rv = __shfl_down_sync(0xffffffffu, vals[i], 2);
        const int   ri = __shfl_down_sync(0xffffffffu, idxs[i], 2);
        if (s == 0 && rv > vmin)
            topk_insert(rv, ri, vals, idxs, vmin, mslot);
    }

    if (s == 0) {
        int* op = g_idx + ((size_t)b * NN + n) * KK;
#pragma unroll
        for (int i = 0; i < KK; i++) op[i] = idxs[i];
    }
}

// ---------------------------------------------------------------------------
// Kernel 2a: layer-1 (edge conv + BN + ReLU) + dual pooling.
// Thread = point, channel = loop -> coalesced m1/m2 stores, edge diffs in regs.
// ---------------------------------------------------------------------------
__global__ void __launch_bounds__(128) edgeA_kernel(
    const float* __restrict__ x,
    const float* __restrict__ w1,  const float* __restrict__ b1,
    const float* __restrict__ g1,  const float* __restrict__ beta1,
    const float* __restrict__ rm1, const float* __restrict__ rv1,
    float* __restrict__ m1o, float* __restrict__ m2o)
{
    __shared__ float sp[HH][8];   // W'*6, bias', pad

    const int tid = threadIdx.x;
    const int b = blockIdx.y;
    const int n = blockIdx.x * 128 + tid;

    if (tid < HH) {
        const float sc = __ldg(g1 + tid) * rsqrtf(__ldg(rv1 + tid) + 1e-5f);
#pragma unroll
        for (int c = 0; c < 6; c++) sp[tid][c] = __ldg(w1 + tid * 6 + c) * sc;
        sp[tid][6] = (__ldg(b1 + tid) - __ldg(rm1 + tid)) * sc + __ldg(beta1 + tid);
    }
    __syncthreads();

    const float* xb = x + (size_t)b * 3 * NN;
    const float c0 = xb[n];
    const float c1 = xb[NN + n];
    const float c2 = xb[2 * NN + n];

    const int* ip = g_idx + ((size_t)b * NN + n) * KK;
    float e0[KK], e1[KK], e2[KK];
#pragma unroll
    for (int k = 0; k < KK; k++) {
        const int m = __ldg(ip + k);
        e0[k] = __ldg(xb + m) - c0;
        e1[k] = __ldg(xb + NN + m) - c1;
        e2[k] = __ldg(xb + 2 * NN + m) - c2;
    }

    const size_t ob = (size_t)b * HH * NN + n;
#pragma unroll 2
    for (int h = 0; h < HH; h++) {
        const float W0 = sp[h][0], W1 = sp[h][1], W2 = sp[h][2];
        const float W3 = sp[h][3], W4 = sp[h][4], W5 = sp[h][5];
        float cd = sp[h][6];
        cd = fmaf(c0, W3, cd);
        cd = fmaf(c1, W4, cd);
        cd = fmaf(c2, W5, cd);

        float mx = -INFINITY, sm = 0.0f;
#pragma unroll
        for (int k = 0; k < KK; k++) {
            float dt = cd;
            dt = fmaf(e0[k], W0, dt);
            dt = fmaf(e1[k], W1, dt);
            dt = fmaf(e2[k], W2, dt);
            dt = fmaxf(dt, 0.0f);
            mx = fmaxf(mx, dt);
            sm += dt;
        }
        m1o[ob + (size_t)h * NN] = mx;
        m2o[ob + (size_t)h * NN] = sm * (1.0f / KK);
    }
}

// ---------------------------------------------------------------------------
// Kernel 2b: layer-2 GEMM: out[b,o,n] = ReLU(BN(sum_c w2[o,c]*cat[b,c,n]))
// 512 threads: 16 float4 n-groups x 32 o-bases, 2 outputs/thread.
// ---------------------------------------------------------------------------
__global__ void __launch_bounds__(512) edgeB_kernel(
    const float* __restrict__ m1o, const float* __restrict__ m2o,
    const float* __restrict__ w2,  const float* __restrict__ b2,
    const float* __restrict__ g2,  const float* __restrict__ beta2,
    const float* __restrict__ rm2, const float* __restrict__ rv2,
    float* __restrict__ out)
{
    __shared__ float sw[DOUT * 129];   // [o][c] padded rows
    __shared__ float ssc[DOUT], sbi[DOUT];

    const int tid = threadIdx.x;
    for (int i = tid; i < DOUT * 2 * HH; i += 512) {
        const int o = i >> 7, c = i & 127;
        sw[o * 129 + c] = __ldg(w2 + i);
    }
    if (tid < DOUT) {
        const float sc = __ldg(g2 + tid) * rsqrtf(__ldg(rv2 + tid) + 1e-5f);
        ssc[tid] = sc;
        sbi[tid] = (__ldg(b2 + tid) - __ldg(rm2 + tid)) * sc + __ldg(beta2 + tid);
    }
    __syncthreads();

    const int n4    = tid & 15;        // 16 float4 groups -> 64 n per block
    const int obase = tid >> 4;        // 0..31, thread covers o = obase+32j
    const int b  = blockIdx.y;
    const int n0 = blockIdx.x * 64 + n4 * 4;

    float4 acc[2];
#pragma unroll
    for (int j = 0; j < 2; j++) acc[j] = make_float4(0.f, 0.f, 0.f, 0.f);

    const float* cat0 = m1o + (size_t)b * HH * NN + n0;
    const float* cat1 = m2o + (size_t)b * HH * NN + n0;

#pragma unroll 4
    for (int c = 0; c < HH; c++) {
        const float4 v = __ldg(reinterpret_cast<const float4*>(cat0 + (size_t)c * NN));
#pragma unroll
        for (int j = 0; j < 2; j++) {
            const float w = sw[(obase + 32 * j) * 129 + c];
            acc[j].x = fmaf(w, v.x, acc[j].x);
            acc[j].y = fmaf(w, v.y, acc[j].y);
            acc[j].z = fmaf(w, v.z, acc[j].z);
            acc[j].w = fmaf(w, v.w, acc[j].w);
        }
    }
#pragma unroll 4
    for (int c = 0; c < HH; c++) {
        const float4 v = __ldg(reinterpret_cast<const float4*>(cat1 + (size_t)c * NN));
#pragma unroll
        for (int j = 0; j < 2; j++) {
            const float w = sw[(obase + 32 * j) * 129 + HH + c];
            acc[j].x = fmaf(w, v.x, acc[j].x);
            acc[j].y = fmaf(w, v.y, acc[j].y);
            acc[j].z = fmaf(w, v.z, acc[j].z);
            acc[j].w = fmaf(w, v.w, acc[j].w);
        }
    }

#pragma unroll
    for (int j = 0; j < 2; j++) {
        const int o = obase + 32 * j;
        const float sc = ssc[o], bi = sbi[o];
        float4 r;
        r.x = fmaxf(fmaf(acc[j].x, sc, bi), 0.0f);
        r.y = fmaxf(fmaf(acc[j].y, sc, bi), 0.0f);
        r.z = fmaxf(fmaf(acc[j].z, sc, bi), 0.0f);
        r.w = fmaxf(fmaf(acc[j].w, sc, bi), 0.0f);
        *reinterpret_cast<float4*>(out + ((size_t)b * DOUT + o) * NN + n0) = r;
    }
}

// ---------------------------------------------------------------------------
extern "C" void kernel_launch(void* const* d_in, const int* in_sizes, int n_in,
                              void* d_out, int out_size) {
    const float* x     = (const float*)d_in[0];
    const float* w1    = (const float*)d_in[1];
    const float* b1    = (const float*)d_in[2];
    const float* g1    = (const float*)d_in[3];
    const float* beta1 = (const float*)d_in[4];
    const float* rm1   = (const float*)d_in[5];
    const float* rv1   = (const float*)d_in[6];
    const float* w2    = (const float*)d_in[7];
    const float* b2    = (const float*)d_in[8];
    const float* g2    = (const float*)d_in[9];
    const float* beta2 = (const float*)d_in[10];
    const float* rm2   = (const float*)d_in[11];
    const float* rv2   = (const float*)d_in[12];

    float* out = (float*)d_out;
    float* m1o = out + (size_t)BB * HH * NN;
    float* m2o = m1o + (size_t)BB * HH * NN;

    cudaFuncSetAttribute(knn_kernel,
                         cudaFuncAttributeMaxDynamicSharedMemorySize, KNN_SMEM);

    knn_kernel<<<dim3(NN / QPB, BB), TPB, KNN_SMEM>>>(x);
    edgeA_kernel<<<dim3(NN / 128, BB), 128>>>(x, w1, b1, g1, beta1, rm1, rv1,
                                              m1o, m2o);
    edgeB_kernel<<<dim3(NN / 64, BB), 512>>>(m1o, m2o, w2, b2, g2, beta2,
                                             rm2, rv2, out);
}

// round 17
// speedup vs baseline: 2.5161x; 1.3693x over previous
#include <cuda_runtime.h>
#include <math.h>

#define BB   8
#define NN   4096
#define KK   20
#define HH   64
#define DOUT 64

#define QPB   128                // queries per block
#define SPLIT 2                  // lanes per query (candidate-range split)
#define TPB   (QPB * SPLIT)      // 256
#define SUBR  1024               // sub-range length (pad segment size)

#define BUFSLOTS 24
#define CLOUD_BYTES ((NN + 4) * 16)                 // float4[4100] = 65600
#define KNN_SMEM (CLOUD_BYTES + BUFSLOTS * TPB * 8) // + 49152 = 114752 B

// scratch for KNN indices (allocation-free rule: __device__ global)
__device__ int g_idx[BB * NN * KK];

__device__ __forceinline__ void topk_insert(float d, int m,
                                            float (&vals)[KK], int (&idxs)[KK],
                                            float& vmin, int& mslot) {
#pragma unroll
    for (int i = 0; i < KK; i++)
        if (i == mslot) { vals[i] = d; idxs[i] = m; }
    vmin = vals[0]; mslot = 0;
#pragma unroll
    for (int i = 1; i < KK; i++)
        if (vals[i] < vmin) { vmin = vals[i]; mslot = i; }
}

// branchless next-float-toward -inf; -inf maps to NaN which fmaxf suppresses
__device__ __forceinline__ float pred_f(float x) {
    const unsigned u = __float_as_uint(x);
    const unsigned up = (x > 0.0f) ? (u - 1u) : (u + 1u);
    return (x == 0.0f) ? -1.401298464e-45f : __uint_as_float(up);
}

// ---------------------------------------------------------------------------
// Kernel 1: brute-force KNN. 2 lanes split the candidate range per query.
// Candidate buffer lives in SMEM ([slot][tid], conflict-free). Scan pushes are
// gated by thr = max(vmin_own, pred(vmin_partner)):  d > thr  ===
// (d > vmin_own) && (d >= vmin_partner) -- prunes candidates that cannot
// survive the 2-list merge (merged 20th >= max of partial 20ths); pred keeps
// exact-tie semantics. Flush check once per 16 candidates (buffer 24 slots:
// cnt<=8 at check + 16 max growth). Partial lists merged with one shfl_down.
// Ranking key: d' = 2*inner(n,m) - xx[m]  (== dist + xx[n], order-equivalent)
// ---------------------------------------------------------------------------
__global__ void __launch_bounds__(TPB) knn_kernel(const float* __restrict__ x) {
    extern __shared__ char smem[];
    float4* sx4  = reinterpret_cast<float4*>(smem);        // (x,y,z,-xx), pad/1024
    float2* sbuf = reinterpret_cast<float2*>(smem + CLOUD_BYTES);

    const int tid = threadIdx.x;
    const int b   = blockIdx.y;
    const int n0  = blockIdx.x * QPB;
    const float* xb = x + (size_t)b * 3 * NN;

    for (int i = tid; i < NN; i += TPB) {
        const float x0 = xb[i], x1 = xb[NN + i], x2 = xb[2 * NN + i];
        float w = -x0 * x0;
        w = fmaf(-x1, x1, w);
        w = fmaf(-x2, x2, w);
        sx4[i + (i >> 10)] = make_float4(x0, x1, x2, w);
    }
    __syncthreads();

    const int q = tid >> 1, s = tid & 1;
    const int n = n0 + q;
    const float4 ctr = sx4[n + (n >> 10)];
    const float a0 = 2.0f * ctr.x, a1 = 2.0f * ctr.y, a2 = 2.0f * ctr.z;

    float vals[KK];
    int   idxs[KK];
#pragma unroll
    for (int i = 0; i < KK; i++) { vals[i] = -INFINITY; idxs[i] = 0; }
    float vmin = -INFINITY;
    float thr  = -INFINITY;
    int   mslot = 0;
    int   cnt = 0;

    // lane s covers sub-ranges 2s and 2s+1 (each 1024, pad-rebased pointers)
#pragma unroll 1
    for (int h = 0; h < 2; h++) {
        const int seg = s * 2 + h;
        const float4* base = sx4 + seg * (SUBR + 1);
        const int mbase = seg * SUBR;

        for (int j0 = 0; j0 < SUBR; j0 += 16) {
            // two unrolled 8-candidate groups, one vote/flush check per 16
#pragma unroll
            for (int g = 0; g < 2; g++) {
                float d[8];
#pragma unroll
                for (int u = 0; u < 8; u++) {
                    const float4 p = base[j0 + g * 8 + u];
                    float dd = fmaf(a2, p.z, p.w);
                    dd = fmaf(a1, p.y, dd);
                    dd = fmaf(a0, p.x, dd);
                    d[u] = dd;
                }
#pragma unroll
                for (int u = 0; u < 8; u++) {
                    if (d[u] > thr) {
                        sbuf[cnt * TPB + tid] =
                            make_float2(d[u], __int_as_float(mbase + j0 + g * 8 + u));
                        cnt++;
                    }
                }
            }
            if (__any_sync(0xffffffffu, cnt >= 8)) {
                for (int j = 0; j < cnt; j++) {
                    const float2 t = sbuf[j * TPB + tid];
                    if (t.x > vmin)
                        topk_insert(t.x, __float_as_int(t.y),
                                    vals, idxs, vmin, mslot);
                }
                cnt = 0;
                const float pmin = __shfl_xor_sync(0xffffffffu, vmin, 1);
                thr = fmaxf(vmin, pred_f(pmin));
            }
        }
    }
    for (int j = 0; j < cnt; j++) {
        const float2 t = sbuf[j * TPB + tid];
        if (t.x > vmin)
            topk_insert(t.x, __float_as_int(t.y), vals, idxs, vmin, mslot);
    }

    // ---- merge: lane s=0 (lower range) receives s=1's list; strict '>'
    // keeps the lowest index on exact ties (matches jax.lax.top_k).
#pragma unroll
    for (int i = 0; i < KK; i++) {
        const float rv = __shfl_down_sync(0xffffffffu, vals[i], 1);
        const int   ri = __shfl_down_sync(0xffffffffu, idxs[i], 1);
        if (s == 0 && rv > vmin)
            topk_insert(rv, ri, vals, idxs, vmin, mslot);
    }

    if (s == 0) {
        int* op = g_idx + ((size_t)b * NN + n) * KK;
#pragma unroll
        for (int i = 0; i < KK; i++) op[i] = idxs[i];
    }
}

// ---------------------------------------------------------------------------
// Kernel 2a: layer-1 (edge conv + BN + ReLU) + dual pooling.
// Thread = point, channel = loop -> coalesced m1/m2 stores, edge diffs in regs.
// ---------------------------------------------------------------------------
__global__ void __launch_bounds__(128) edgeA_kernel(
    const float* __restrict__ x,
    const float* __restrict__ w1,  const float* __restrict__ b1,
    const float* __restrict__ g1,  const float* __restrict__ beta1,
    const float* __restrict__ rm1, const float* __restrict__ rv1,
    float* __restrict__ m1o, float* __restrict__ m2o)
{
    __shared__ float sp[HH][8];   // W'*6, bias', pad

    const int tid = threadIdx.x;
    const int b = blockIdx.y;
    const int n = blockIdx.x * 128 + tid;

    if (tid < HH) {
        const float sc = __ldg(g1 + tid) * rsqrtf(__ldg(rv1 + tid) + 1e-5f);
#pragma unroll
        for (int c = 0; c < 6; c++) sp[tid][c] = __ldg(w1 + tid * 6 + c) * sc;
        sp[tid][6] = (__ldg(b1 + tid) - __ldg(rm1 + tid)) * sc + __ldg(beta1 + tid);
    }
    __syncthreads();

    const float* xb = x + (size_t)b * 3 * NN;
    const float c0 = xb[n];
    const float c1 = xb[NN + n];
    const float c2 = xb[2 * NN + n];

    const int* ip = g_idx + ((size_t)b * NN + n) * KK;
    float e0[KK], e1[KK], e2[KK];
#pragma unroll
    for (int k = 0; k < KK; k++) {
        const int m = __ldg(ip + k);
        e0[k] = __ldg(xb + m) - c0;
        e1[k] = __ldg(xb + NN + m) - c1;
        e2[k] = __ldg(xb + 2 * NN + m) - c2;
    }

    const size_t ob = (size_t)b * HH * NN + n;
#pragma unroll 2
    for (int h = 0; h < HH; h++) {
        const float W0 = sp[h][0], W1 = sp[h][1], W2 = sp[h][2];
        const float W3 = sp[h][3], W4 = sp[h][4], W5 = sp[h][5];
        float cd = sp[h][6];
        cd = fmaf(c0, W3, cd);
        cd = fmaf(c1, W4, cd);
        cd = fmaf(c2, W5, cd);

        float mx = -INFINITY, sm = 0.0f;
#pragma unroll
        for (int k = 0; k < KK; k++) {
            float dt = cd;
            dt = fmaf(e0[k], W0, dt);
            dt = fmaf(e1[k], W1, dt);
            dt = fmaf(e2[k], W2, dt);
            dt = fmaxf(dt, 0.0f);
            mx = fmaxf(mx, dt);
            sm += dt;
        }
        m1o[ob + (size_t)h * NN] = mx;
        m2o[ob + (size_t)h * NN] = sm * (1.0f / KK);
    }
}

// ---------------------------------------------------------------------------
// Kernel 2b: layer-2 GEMM: out[b,o,n] = ReLU(BN(sum_c w2[o,c]*cat[b,c,n]))
// 512 threads: 16 float4 n-groups x 32 o-bases, 2 outputs/thread.
// ---------------------------------------------------------------------------
__global__ void __launch_bounds__(512) edgeB_kernel(
    const float* __restrict__ m1o, const float* __restrict__ m2o,
    const float* __restrict__ w2,  const float* __restrict__ b2,
    const float* __restrict__ g2,  const float* __restrict__ beta2,
    const float* __restrict__ rm2, const float* __restrict__ rv2,
    float* __restrict__ out)
{
    __shared__ float sw[DOUT * 129];   // [o][c] padded rows
    __shared__ float ssc[DOUT], sbi[DOUT];

    const int tid = threadIdx.x;
    for (int i = tid; i < DOUT * 2 * HH; i += 512) {
        const int o = i >> 7, c = i & 127;
        sw[o * 129 + c] = __ldg(w2 + i);
    }
    if (tid < DOUT) {
        const float sc = __ldg(g2 + tid) * rsqrtf(__ldg(rv2 + tid) + 1e-5f);
        ssc[tid] = sc;
        sbi[tid] = (__ldg(b2 + tid) - __ldg(rm2 + tid)) * sc + __ldg(beta2 + tid);
    }
    __syncthreads();

    const int n4    = tid & 15;        // 16 float4 groups -> 64 n per block
    const int obase = tid >> 4;        // 0..31, thread covers o = obase+32j
    const int b  = blockIdx.y;
    const int n0 = blockIdx.x * 64 + n4 * 4;

    float4 acc[2];
#pragma unroll
    for (int j = 0; j < 2; j++) acc[j] = make_float4(0.f, 0.f, 0.f, 0.f);

    const float* cat0 = m1o + (size_t)b * HH * NN + n0;
    const float* cat1 = m2o + (size_t)b * HH * NN + n0;

#pragma unroll 4
    for (int c = 0; c < HH; c++) {
        const float4 v = __ldg(reinterpret_cast<const float4*>(cat0 + (size_t)c * NN));
#pragma unroll
        for (int j = 0; j < 2; j++) {
            const float w = sw[(obase + 32 * j) * 129 + c];
            acc[j].x = fmaf(w, v.x, acc[j].x);
            acc[j].y = fmaf(w, v.y, acc[j].y);
            acc[j].z = fmaf(w, v.z, acc[j].z);
            acc[j].w = fmaf(w, v.w, acc[j].w);
        }
    }
#pragma unroll 4
    for (int c = 0; c < HH; c++) {
        const float4 v = __ldg(reinterpret_cast<const float4*>(cat1 + (size_t)c * NN));
#pragma unroll
        for (int j = 0; j < 2; j++) {
            const float w = sw[(obase + 32 * j) * 129 + HH + c];
            acc[j].x = fmaf(w, v.x, acc[j].x);
            acc[j].y = fmaf(w, v.y, acc[j].y);
            acc[j].z = fmaf(w, v.z, acc[j].z);
            acc[j].w = fmaf(w, v.w, acc[j].w);
        }
    }

#pragma unroll
    for (int j = 0; j < 2; j++) {
        const int o = obase + 32 * j;
        const float sc = ssc[o], bi = sbi[o];
        float4 r;
        r.x = fmaxf(fmaf(acc[j].x, sc, bi), 0.0f);
        r.y = fmaxf(fmaf(acc[j].y, sc, bi), 0.0f);
        r.z = fmaxf(fmaf(acc[j].z, sc, bi), 0.0f);
        r.w = fmaxf(fmaf(acc[j].w, sc, bi), 0.0f);
        *reinterpret_cast<float4*>(out + ((size_t)b * DOUT + o) * NN + n0) = r;
    }
}

// ---------------------------------------------------------------------------
extern "C" void kernel_launch(void* const* d_in, const int* in_sizes, int n_in,
                              void* d_out, int out_size) {
    const float* x     = (const float*)d_in[0];
    const float* w1    = (const float*)d_in[1];
    const float* b1    = (const float*)d_in[2];
    const float* g1    = (const float*)d_in[3];
    const float* beta1 = (const float*)d_in[4];
    const float* rm1   = (const float*)d_in[5];
    const float* rv1   = (const float*)d_in[6];
    const float* w2    = (const float*)d_in[7];
    const float* b2    = (const float*)d_in[8];
    const float* g2    = (const float*)d_in[9];
    const float* beta2 = (const float*)d_in[10];
    const float* rm2   = (const float*)d_in[11];
    const float* rv2   = (const float*)d_in[12];

    float* out = (float*)d_out;
    float* m1o = out + (size_t)BB * HH * NN;
    float* m2o = m1o + (size_t)BB * HH * NN;

    cudaFuncSetAttribute(knn_kernel,
                         cudaFuncAttributeMaxDynamicSharedMemorySize, KNN_SMEM);

    knn_kernel<<<dim3(NN / QPB, BB), TPB, KNN_SMEM>>>(x);
    edgeA_kernel<<<dim3(NN / 128, BB), 128>>>(x, w1, b1, g1, beta1, rm1, rv1,
                                              m1o, m2o);
    edgeB_kernel<<<dim3(NN / 64, BB), 512>>>(m1o, m2o, w2, b2, g2, beta2,
                                             rm2, rv2, out);
}